// round 3
// baseline (speedup 1.0000x reference)
#include <cuda_runtime.h>

// VectorKuramoto factorized:
//   sum_j A*sin(tj - ti - a) = ci*P - si*Q
//   P = sum_j (A cos a) sj - (A sin a) cj ; Q = sum_j (A cos a) cj + (A sin a) sj
// Persistent uniform grid (2 CTAs per SM), 4-row work units, f32x2 packed FMA.

namespace {

constexpr int Bb = 4;
constexpr int Nn = 2048;
constexpr int N4 = Nn / 4;             // 512 float4 per row
constexpr int THREADS = 512;           // 16 warps: 2 row-pairs x 8 j-slices
constexpr int UNITS = (Bb * Nn) / 4;   // 2048 four-row units

__device__ __host__ __forceinline__ int padidx(int i) { return i + (i >> 3); }
constexpr int PAD_N = Nn + (Nn >> 3);  // 2304 float4 slots per table
constexpr int RED_F4 = 2 * 8 * 4;      // [pair][slice][P0,Q0,P1,Q1]
constexpr int SMEM_BYTES = (2 * PAD_N + RED_F4) * (int)sizeof(float4); // 74752 B

typedef unsigned long long ull;

#define FMA2(d, a, b, c) \
    asm("fma.rn.f32x2 %0, %1, %2, %3;" : "=l"(d) : "l"(a), "l"(b), "l"(c))
#define PACK2(d, lo, hi) \
    asm("mov.b64 %0, {%1, %2};" : "=l"(d) : "f"(lo), "f"(hi))
#define UNPACK2(lo, hi, s) \
    asm("mov.b64 {%0, %1}, %2;" : "=f"(lo), "=f"(hi) : "l"(s))

union F4U { float4 v; ull u[2]; };

__device__ __forceinline__ void cell(float A, float a,
                                     ull sj01, ull sj23, ull cj01, ull cj23,
                                     ull& Pa, ull& Pb, ull& Qa, ull& Qb)
{
    float sa, ca;
    __sincosf(a, &sa, &ca);
    float w1 = A * ca;
    float w2 = A * sa;
    float nw2 = -w2;
    ull pw1, pw2, pnw2;
    PACK2(pw1, w1, w1);
    PACK2(pw2, w2, w2);
    PACK2(pnw2, nw2, nw2);
    FMA2(Pa, pnw2, cj01, Pa); FMA2(Pa, pw1, sj01, Pa);
    FMA2(Pb, pnw2, cj23, Pb); FMA2(Pb, pw1, sj23, Pb);
    FMA2(Qa, pw2,  sj01, Qa); FMA2(Qa, pw1, cj01, Qa);
    FMA2(Qb, pw2,  sj23, Qb); FMA2(Qb, pw1, cj23, Qb);
}

} // namespace

extern "C" __global__ void __launch_bounds__(THREADS, 2)
vector_kuramoto_kernel(const float4* __restrict__ theta4,
                       const float4* __restrict__ gamma4,
                       const float4* __restrict__ aff4,
                       const float4* __restrict__ alpha4,
                       const float4* __restrict__ omega4,
                       const float4* __restrict__ kappa4,
                       const float4* __restrict__ abias4,
                       float4* __restrict__ out4)
{
    extern __shared__ float4 smem[];
    float4* s4  = smem;                 // sin(theta[b,r,:]) at padidx(r)
    float4* c4  = smem + PAD_N;         // cos(theta[b,r,:]) at padidx(r)
    float4* red = smem + 2 * PAD_N;     // reduction buffer

    const int tid  = threadIdx.x;
    const int warp = tid >> 5;
    const int lane = tid & 31;
    const int pair  = warp >> 3;        // 0..1  (rows 2p, 2p+1 of the unit)
    const int slice = warp & 7;         // 0..7  (64 float4 of j each)

    const int G  = gridDim.x;
    const int u0 = (int)(((long long)blockIdx.x       * UNITS) / G);
    const int u1 = (int)(((long long)(blockIdx.x + 1) * UNITS) / G);

    int cur_b = -1;

    for (int u = u0; u < u1; ++u) {
        const int b    = u >> 9;             // UNITS per batch = 512
        const int tile = (u & 511) << 2;     // base row within batch

        if (b != cur_b) {
            __syncthreads();                 // prior readers of tables done
            for (int r = tid; r < Nn; r += THREADS) {
                float4 th = theta4[b * Nn + r];
                float4 s, c;
                __sincosf(th.x, &s.x, &c.x);
                __sincosf(th.y, &s.y, &c.y);
                __sincosf(th.z, &s.z, &c.z);
                __sincosf(th.w, &s.w, &c.w);
                s4[padidx(r)] = s;
                c4[padidx(r)] = c;
            }
            cur_b = b;
            __syncthreads();
        }

        const int i0  = tile + (pair << 1);
        const int rb0 = ((b << 11) + i0) << 9;   // (b*Nn+i0)*N4, fits int
        const int rb1 = rb0 + N4;
        const int bb0 = i0 << 9;
        const int bb1 = bb0 + N4;

        ull P0a = 0, P0b = 0, Q0a = 0, Q0b = 0;
        ull P1a = 0, P1b = 0, Q1a = 0, Q1b = 0;

        #pragma unroll
        for (int k = 0; k < 2; ++k) {
            const int jb = (slice << 6) + lane + (k << 5);
            float4 A0 = __ldcs(aff4   + rb0 + jb);
            float4 T0 = __ldcs(alpha4 + rb0 + jb);
            float4 B0 = abias4[bb0 + jb];
            float4 A1 = __ldcs(aff4   + rb1 + jb);
            float4 T1 = __ldcs(alpha4 + rb1 + jb);
            float4 B1 = abias4[bb1 + jb];

            const int j0 = jb << 2;
            F4U sj, cj;
            sj.v = s4[padidx(j0 + 0)]; cj.v = c4[padidx(j0 + 0)];
            cell(A0.x, T0.x + B0.x, sj.u[0], sj.u[1], cj.u[0], cj.u[1], P0a, P0b, Q0a, Q0b);
            cell(A1.x, T1.x + B1.x, sj.u[0], sj.u[1], cj.u[0], cj.u[1], P1a, P1b, Q1a, Q1b);

            sj.v = s4[padidx(j0 + 1)]; cj.v = c4[padidx(j0 + 1)];
            cell(A0.y, T0.y + B0.y, sj.u[0], sj.u[1], cj.u[0], cj.u[1], P0a, P0b, Q0a, Q0b);
            cell(A1.y, T1.y + B1.y, sj.u[0], sj.u[1], cj.u[0], cj.u[1], P1a, P1b, Q1a, Q1b);

            sj.v = s4[padidx(j0 + 2)]; cj.v = c4[padidx(j0 + 2)];
            cell(A0.z, T0.z + B0.z, sj.u[0], sj.u[1], cj.u[0], cj.u[1], P0a, P0b, Q0a, Q0b);
            cell(A1.z, T1.z + B1.z, sj.u[0], sj.u[1], cj.u[0], cj.u[1], P1a, P1b, Q1a, Q1b);

            sj.v = s4[padidx(j0 + 3)]; cj.v = c4[padidx(j0 + 3)];
            cell(A0.w, T0.w + B0.w, sj.u[0], sj.u[1], cj.u[0], cj.u[1], P0a, P0b, Q0a, Q0b);
            cell(A1.w, T1.w + B1.w, sj.u[0], sj.u[1], cj.u[0], cj.u[1], P1a, P1b, Q1a, Q1b);
        }

        // Warp reduction of 16 scalar accumulators.
        float p0[4], q0[4], p1[4], q1[4];
        UNPACK2(p0[0], p0[1], P0a); UNPACK2(p0[2], p0[3], P0b);
        UNPACK2(q0[0], q0[1], Q0a); UNPACK2(q0[2], q0[3], Q0b);
        UNPACK2(p1[0], p1[1], P1a); UNPACK2(p1[2], p1[3], P1b);
        UNPACK2(q1[0], q1[1], Q1a); UNPACK2(q1[2], q1[3], Q1b);

        #pragma unroll
        for (int off = 16; off; off >>= 1) {
            #pragma unroll
            for (int d = 0; d < 4; ++d) {
                p0[d] += __shfl_down_sync(0xffffffffu, p0[d], off);
                q0[d] += __shfl_down_sync(0xffffffffu, q0[d], off);
                p1[d] += __shfl_down_sync(0xffffffffu, p1[d], off);
                q1[d] += __shfl_down_sync(0xffffffffu, q1[d], off);
            }
        }

        if (lane == 0) {
            float4* slot = red + (((pair << 3) + slice) << 2);
            slot[0] = make_float4(p0[0], p0[1], p0[2], p0[3]);
            slot[1] = make_float4(q0[0], q0[1], q0[2], q0[3]);
            slot[2] = make_float4(p1[0], p1[1], p1[2], p1[3]);
            slot[3] = make_float4(q1[0], q1[1], q1[2], q1[3]);
        }
        __syncthreads();

        if (tid < 4) {
            const int r   = tid;            // row within unit
            const int pr  = r >> 1;
            const int sub = r & 1;
            float4 P = make_float4(0.f, 0.f, 0.f, 0.f);
            float4 Q = make_float4(0.f, 0.f, 0.f, 0.f);
            #pragma unroll
            for (int s = 0; s < 8; ++s) {
                float4* slot = red + (((pr << 3) + s) << 2) + (sub << 1);
                float4 pp = slot[0];
                float4 qq = slot[1];
                P.x += pp.x; P.y += pp.y; P.z += pp.z; P.w += pp.w;
                Q.x += qq.x; Q.y += qq.y; Q.z += qq.z; Q.w += qq.w;
            }
            const int i = tile + r;
            const float inv = 1.0f / (float)Nn;   // COUPLING=1, DT=1
            float4 th = theta4[b * Nn + i];
            float4 si = s4[padidx(i)];
            float4 ci = c4[padidx(i)];
            float4 g  = gamma4[b * Nn + i];
            float4 om = omega4[i];
            float4 kp = kappa4[i];
            float4 o;
            o.x = th.x + om.x + kp.x * (g.x - th.x) + inv * (ci.x * P.x - si.x * Q.x);
            o.y = th.y + om.y + kp.y * (g.y - th.y) + inv * (ci.y * P.y - si.y * Q.y);
            o.z = th.z + om.z + kp.z * (g.z - th.z) + inv * (ci.z * P.z - si.z * Q.z);
            o.w = th.w + om.w + kp.w * (g.w - th.w) + inv * (ci.w * P.w - si.w * Q.w);
            out4[b * Nn + i] = o;
        }
        __syncthreads();   // red buffer reusable
    }
}

extern "C" void kernel_launch(void* const* d_in, const int* in_sizes, int n_in,
                              void* d_out, int out_size) {
    (void)in_sizes; (void)n_in; (void)out_size;
    const float4* theta4 = (const float4*)d_in[0];
    const float4* gamma4 = (const float4*)d_in[1];
    const float4* aff4   = (const float4*)d_in[2];
    const float4* alpha4 = (const float4*)d_in[3];
    const float4* omega4 = (const float4*)d_in[4];
    const float4* kappa4 = (const float4*)d_in[5];
    const float4* abias4 = (const float4*)d_in[6];
    float4* out4 = (float4*)d_out;

    static int nsm = 0;
    if (nsm == 0) {
        cudaDeviceProp prop;
        if (cudaGetDeviceProperties(&prop, 0) == cudaSuccess && prop.multiProcessorCount > 0)
            nsm = prop.multiProcessorCount;
        else
            nsm = 148;
        cudaFuncSetAttribute(vector_kuramoto_kernel,
                             cudaFuncAttributeMaxDynamicSharedMemorySize, SMEM_BYTES);
    }

    const int grid = 2 * nsm;   // exactly 2 CTAs per SM, one uniform wave
    vector_kuramoto_kernel<<<grid, THREADS, SMEM_BYTES>>>(
        theta4, gamma4, aff4, alpha4, omega4, kappa4, abias4, out4);
}